// round 3
// baseline (speedup 1.0000x reference)
#include <cuda_runtime.h>
#include <math.h>

#define WIDTH    1024
#define HEADS    16
#define HEAD_DIM 64
#define HIDDEN   4096
#define BATCH    2
#define SEQ      2048
#define ROWS     (BATCH * SEQ)   /* 4096 */
#define BH       (BATCH * HEADS) /* 32 */

// ---------------- scratch (device globals: no allocation allowed) ----------------
__device__ float g_h[ROWS * WIDTH];                     // LN output (reused)
__device__ float g_qkv[ROWS * 3 * WIDTH];               // [4096, 3072]
__device__ float g_scores[(size_t)BH * SEQ * SEQ];      // [32, 2048, 2048]  512 MB
__device__ float g_attnout[ROWS * WIDTH];               // [4096, 1024]
__device__ float g_x1[ROWS * WIDTH];                    // residual after attn
__device__ float g_mlp[(size_t)ROWS * HIDDEN];          // [4096, 4096]

// ---------------- helpers ----------------
__device__ __forceinline__ float gelu_exact(float x) {
    return 0.5f * x * (1.0f + erff(x * 0.70710678118654752440f));
}

__device__ __forceinline__ float block_sum256(float v, volatile float* red) {
    int t = threadIdx.x;
    #pragma unroll
    for (int o = 16; o > 0; o >>= 1) v += __shfl_xor_sync(0xffffffffu, v, o);
    if ((t & 31) == 0) red[t >> 5] = v;
    __syncthreads();
    if (t < 32) {
        float r = (t < 8) ? red[t] : 0.0f;
        #pragma unroll
        for (int o = 4; o > 0; o >>= 1) r += __shfl_xor_sync(0xffffffffu, r, o);
        if (t == 0) red[0] = r;
    }
    __syncthreads();
    float r = red[0];
    __syncthreads();
    return r;
}

__device__ __forceinline__ float block_max256(float v, volatile float* red) {
    int t = threadIdx.x;
    #pragma unroll
    for (int o = 16; o > 0; o >>= 1) v = fmaxf(v, __shfl_xor_sync(0xffffffffu, v, o));
    if ((t & 31) == 0) red[t >> 5] = v;
    __syncthreads();
    if (t < 32) {
        float r = (t < 8) ? red[t] : -INFINITY;
        #pragma unroll
        for (int o = 4; o > 0; o >>= 1) r = fmaxf(r, __shfl_xor_sync(0xffffffffu, r, o));
        if (t == 0) red[0] = r;
    }
    __syncthreads();
    float r = red[0];
    __syncthreads();
    return r;
}

// ---------------- LayerNorm: one block per row (1024 cols, 256 threads x float4) ----------------
__global__ void __launch_bounds__(256) layernorm_kernel(
    const float* __restrict__ x, const float* __restrict__ g,
    const float* __restrict__ b, float* __restrict__ out)
{
    __shared__ float red[32];
    int row = blockIdx.x;
    int t = threadIdx.x;
    const float4* xin = (const float4*)(x + (size_t)row * WIDTH);
    float4 v = xin[t];

    float s = v.x + v.y + v.z + v.w;
    float mu = block_sum256(s, red) * (1.0f / WIDTH);

    float d0 = v.x - mu, d1 = v.y - mu, d2 = v.z - mu, d3 = v.w - mu;
    float ss = d0 * d0 + d1 * d1 + d2 * d2 + d3 * d3;
    float var = block_sum256(ss, red) * (1.0f / WIDTH);
    float rstd = rsqrtf(var + 1e-5f);

    float4 gg = ((const float4*)g)[t];
    float4 bb = ((const float4*)b)[t];
    float4 o4;
    o4.x = d0 * rstd * gg.x + bb.x;
    o4.y = d1 * rstd * gg.y + bb.y;
    o4.z = d2 * rstd * gg.z + bb.z;
    o4.w = d3 * rstd * gg.w + bb.w;
    ((float4*)(out + (size_t)row * WIDTH))[t] = o4;
}

// ---------------- Generic SGEMM: C[M,N] = A[M,K] @ B[K,N], 128x128x8, 256 thr, 8x8/thr --------
// EPI: 0 = none, 2 = +bias +residual, 3 = +bias +exact GELU
template <int EPI>
__global__ void __launch_bounds__(256) sgemm_kernel(
    const float* __restrict__ A, const float* __restrict__ B, float* __restrict__ C,
    const float* __restrict__ bias, const float* __restrict__ res,
    int M, int N, int K, int lda, int ldb, int ldc)
{
    __shared__ float As[8][128];
    __shared__ float Bs[8][128];

    const int bm = blockIdx.y * 128;
    const int bn = blockIdx.x * 128;
    const int tid = threadIdx.x;
    const int tr = (tid >> 4) << 3;  // 0..120
    const int tc = (tid & 15) << 3;

    float acc[8][8];
    #pragma unroll
    for (int i = 0; i < 8; i++)
        #pragma unroll
        for (int j = 0; j < 8; j++) acc[i][j] = 0.0f;

    const int a_row = tid >> 1;        // 0..127
    const int a_k   = (tid & 1) << 2;  // 0 or 4
    const int b_k   = tid >> 5;        // 0..7
    const int b_col = (tid & 31) << 2; // 0..124

    const bool avalid = (bm + a_row) < M;
    const bool bvalid = (bn + b_col) < N;
    const float* Aptr = A + (size_t)(bm + a_row) * lda + a_k;
    const float* Bptr = B + (size_t)b_k * ldb + bn + b_col;

    for (int kk = 0; kk < K; kk += 8) {
        float4 av = avalid ? *(const float4*)Aptr : make_float4(0.f, 0.f, 0.f, 0.f);
        float4 bv = bvalid ? *(const float4*)Bptr : make_float4(0.f, 0.f, 0.f, 0.f);
        __syncthreads();
        As[a_k + 0][a_row] = av.x;
        As[a_k + 1][a_row] = av.y;
        As[a_k + 2][a_row] = av.z;
        As[a_k + 3][a_row] = av.w;
        *(float4*)&Bs[b_k][b_col] = bv;
        __syncthreads();
        #pragma unroll
        for (int k = 0; k < 8; k++) {
            float4 a0 = *(const float4*)&As[k][tr];
            float4 a1 = *(const float4*)&As[k][tr + 4];
            float4 b0 = *(const float4*)&Bs[k][tc];
            float4 b1 = *(const float4*)&Bs[k][tc + 4];
            float aa[8] = {a0.x, a0.y, a0.z, a0.w, a1.x, a1.y, a1.z, a1.w};
            float bb[8] = {b0.x, b0.y, b0.z, b0.w, b1.x, b1.y, b1.z, b1.w};
            #pragma unroll
            for (int i = 0; i < 8; i++)
                #pragma unroll
                for (int j = 0; j < 8; j++) acc[i][j] = fmaf(aa[i], bb[j], acc[i][j]);
        }
        Aptr += 8;
        Bptr += (size_t)8 * ldb;
    }

    #pragma unroll
    for (int i = 0; i < 8; i++) {
        int row = bm + tr + i;
        if (row >= M) continue;
        #pragma unroll
        for (int j = 0; j < 8; j++) {
            int col = bn + tc + j;
            if (col >= N) continue;
            float v = acc[i][j];
            if (EPI >= 2) v += bias[col];
            if (EPI == 2) v += res[(size_t)row * ldc + col];
            if (EPI == 3) v = gelu_exact(v);
            C[(size_t)row * ldc + col] = v;
        }
    }
}

// ---------------- attention scores: S[bh,i,j] = scale * q_i . k_j  (64x64 tile, K=64) --------
__global__ void __launch_bounds__(256) attn_scores_kernel(
    const float* __restrict__ qkv, float* __restrict__ S)
{
    __shared__ float Qs[64][68];  // transposed: Qs[d][i]
    __shared__ float Ks[64][68];  // transposed: Ks[d][j]

    const int jt = blockIdx.x;   // key tile
    const int it = blockIdx.y;   // query tile
    const int bh = blockIdx.z;
    const int b = bh >> 4, h = bh & 15;
    const int tid = threadIdx.x;

    const size_t qbase = (size_t)(b * SEQ + it * 64) * 3072 + h * 64;
    const size_t kbase = (size_t)(b * SEQ + jt * 64) * 3072 + 1024 + h * 64;

    #pragma unroll
    for (int q = 0; q < 4; q++) {
        int f = tid + 256 * q;        // float4 index 0..1023
        int row = f >> 4;             // 0..63
        int c4 = (f & 15) << 2;       // 0..60
        float4 qv = *(const float4*)(qkv + qbase + (size_t)row * 3072 + c4);
        float4 kv = *(const float4*)(qkv + kbase + (size_t)row * 3072 + c4);
        Qs[c4 + 0][row] = qv.x; Qs[c4 + 1][row] = qv.y;
        Qs[c4 + 2][row] = qv.z; Qs[c4 + 3][row] = qv.w;
        Ks[c4 + 0][row] = kv.x; Ks[c4 + 1][row] = kv.y;
        Ks[c4 + 2][row] = kv.z; Ks[c4 + 3][row] = kv.w;
    }
    __syncthreads();

    const int ti = (tid >> 4) << 2;  // 0..60
    const int tj = (tid & 15) << 2;  // 0..60
    float acc[4][4] = {};
    #pragma unroll 8
    for (int d = 0; d < 64; d++) {
        float4 a = *(const float4*)&Qs[d][ti];
        float4 bb = *(const float4*)&Ks[d][tj];
        float aa[4] = {a.x, a.y, a.z, a.w};
        float bv[4] = {bb.x, bb.y, bb.z, bb.w};
        #pragma unroll
        for (int i = 0; i < 4; i++)
            #pragma unroll
            for (int j = 0; j < 4; j++) acc[i][j] = fmaf(aa[i], bv[j], acc[i][j]);
    }

    const float scale = 0.125f;  // 1/sqrt(64)
    size_t base = (size_t)bh * SEQ * SEQ;
    #pragma unroll
    for (int i = 0; i < 4; i++) {
        size_t roff = base + (size_t)(it * 64 + ti + i) * SEQ + jt * 64 + tj;
        float4 o;
        o.x = acc[i][0] * scale; o.y = acc[i][1] * scale;
        o.z = acc[i][2] * scale; o.w = acc[i][3] * scale;
        *(float4*)(S + roff) = o;
    }
}

// ---------------- softmax over rows of S (row = 2048) ----------------
__global__ void __launch_bounds__(256) softmax_kernel(float* __restrict__ S)
{
    __shared__ float red[32];
    size_t row = (size_t)blockIdx.y * SEQ + blockIdx.x;
    float* p = S + row * SEQ;
    int t = threadIdx.x;

    float4 a = ((const float4*)p)[t];
    float4 b = ((const float4*)p)[t + 256];
    float m = fmaxf(fmaxf(fmaxf(a.x, a.y), fmaxf(a.z, a.w)),
                    fmaxf(fmaxf(b.x, b.y), fmaxf(b.z, b.w)));
    m = block_max256(m, red);

    a.x = expf(a.x - m); a.y = expf(a.y - m); a.z = expf(a.z - m); a.w = expf(a.w - m);
    b.x = expf(b.x - m); b.y = expf(b.y - m); b.z = expf(b.z - m); b.w = expf(b.w - m);
    float s = a.x + a.y + a.z + a.w + b.x + b.y + b.z + b.w;
    s = block_sum256(s, red);
    float inv = 1.0f / s;

    a.x *= inv; a.y *= inv; a.z *= inv; a.w *= inv;
    b.x *= inv; b.y *= inv; b.z *= inv; b.w *= inv;
    ((float4*)p)[t] = a;
    ((float4*)p)[t + 256] = b;
}

// ---------------- PV: out[., h*64+d] = S[bh] @ V[bh]   (128x64 tile, K=2048) ----------------
__global__ void __launch_bounds__(256) attn_pv_kernel(
    const float* __restrict__ S, const float* __restrict__ qkv, float* __restrict__ out)
{
    __shared__ float As[8][128];
    __shared__ float Bs[8][64];

    const int bh = blockIdx.y;
    const int b = bh >> 4, h = bh & 15;
    const float* A = S + (size_t)bh * SEQ * SEQ;
    const float* V = qkv + (size_t)b * SEQ * 3072 + 2048 + h * 64;
    float* C = out + (size_t)b * SEQ * WIDTH + h * 64;

    const int bm = blockIdx.x * 128;
    const int tid = threadIdx.x;
    const int tr = (tid >> 3) << 2;  // 0..124 (4 rows)
    const int tc = (tid & 7) << 3;   // 0..56  (8 cols)

    float acc[4][8];
    #pragma unroll
    for (int i = 0; i < 4; i++)
        #pragma unroll
        for (int j = 0; j < 8; j++) acc[i][j] = 0.0f;

    const int a_row = tid >> 1;
    const int a_k   = (tid & 1) << 2;
    const int b_k   = tid >> 4;        // 0..15 (only tid<128 load)
    const int b_col = (tid & 15) << 2; // 0..60

    const float* Aptr = A + (size_t)(bm + a_row) * SEQ + a_k;
    const float* Bptr = V + (size_t)b_k * 3072 + b_col;

    for (int kk = 0; kk < SEQ; kk += 8) {
        float4 av = *(const float4*)Aptr;
        float4 bv = make_float4(0.f, 0.f, 0.f, 0.f);
        if (tid < 128) bv = *(const float4*)Bptr;
        __syncthreads();
        As[a_k + 0][a_row] = av.x;
        As[a_k + 1][a_row] = av.y;
        As[a_k + 2][a_row] = av.z;
        As[a_k + 3][a_row] = av.w;
        if (tid < 128) *(float4*)&Bs[b_k][b_col] = bv;
        __syncthreads();
        #pragma unroll
        for (int k = 0; k < 8; k++) {
            float4 a0 = *(const float4*)&As[k][tr];
            float4 b0 = *(const float4*)&Bs[k][tc];
            float4 b1 = *(const float4*)&Bs[k][tc + 4];
            float aa[4] = {a0.x, a0.y, a0.z, a0.w};
            float bb[8] = {b0.x, b0.y, b0.z, b0.w, b1.x, b1.y, b1.z, b1.w};
            #pragma unroll
            for (int i = 0; i < 4; i++)
                #pragma unroll
                for (int j = 0; j < 8; j++) acc[i][j] = fmaf(aa[i], bb[j], acc[i][j]);
        }
        Aptr += 8;
        Bptr += (size_t)8 * 3072;
    }

    #pragma unroll
    for (int i = 0; i < 4; i++) {
        #pragma unroll
        for (int j = 0; j < 8; j += 4) {
            float4 o;
            o.x = acc[i][j + 0]; o.y = acc[i][j + 1];
            o.z = acc[i][j + 2]; o.w = acc[i][j + 3];
            *(float4*)(C + (size_t)(bm + tr + i) * WIDTH + tc + j) = o;
        }
    }
}

// ---------------- launch ----------------
extern "C" void kernel_launch(void* const* d_in, const int* in_sizes, int n_in,
                              void* d_out, int out_size)
{
    const float* x      = (const float*)d_in[0];
    const float* ln1_g  = (const float*)d_in[1];
    const float* ln1_b  = (const float*)d_in[2];
    const float* w_qkv  = (const float*)d_in[3];
    const float* w_proj = (const float*)d_in[4];
    const float* b_proj = (const float*)d_in[5];
    const float* ln2_g  = (const float*)d_in[6];
    const float* ln2_b  = (const float*)d_in[7];
    const float* w_fc1  = (const float*)d_in[8];
    const float* b_fc1  = (const float*)d_in[9];
    const float* w_fc2  = (const float*)d_in[10];
    const float* b_fc2  = (const float*)d_in[11];
    float* out = (float*)d_out;

    float *ph, *pqkv, *pscore, *pattn, *px1, *pmlp;
    cudaGetSymbolAddress((void**)&ph,     g_h);
    cudaGetSymbolAddress((void**)&pqkv,   g_qkv);
    cudaGetSymbolAddress((void**)&pscore, g_scores);
    cudaGetSymbolAddress((void**)&pattn,  g_attnout);
    cudaGetSymbolAddress((void**)&px1,    g_x1);
    cudaGetSymbolAddress((void**)&pmlp,   g_mlp);

    // 1) LN1
    layernorm_kernel<<<ROWS, 256>>>(x, ln1_g, ln1_b, ph);
    // 2) QKV GEMM: [4096,1024] @ [1024,3072]
    sgemm_kernel<0><<<dim3(3072 / 128, ROWS / 128), 256>>>(
        ph, w_qkv, pqkv, nullptr, nullptr, ROWS, 3072, 1024, 1024, 3072, 3072);
    // 3) scores
    attn_scores_kernel<<<dim3(SEQ / 64, SEQ / 64, BH), 256>>>(pqkv, pscore);
    // 4) softmax
    softmax_kernel<<<dim3(SEQ, BH), 256>>>(pscore);
    // 5) PV
    attn_pv_kernel<<<dim3(SEQ / 128, BH), 256>>>(pscore, pqkv, pattn);
    // 6) proj + bias + residual(x)
    sgemm_kernel<2><<<dim3(WIDTH / 128, ROWS / 128), 256>>>(
        pattn, w_proj, px1, b_proj, x, ROWS, WIDTH, 1024, 1024, WIDTH, WIDTH);
    // 7) LN2
    layernorm_kernel<<<ROWS, 256>>>(px1, ln2_g, ln2_b, ph);
    // 8) fc1 + bias + exact GELU
    sgemm_kernel<3><<<dim3(HIDDEN / 128, ROWS / 128), 256>>>(
        ph, w_fc1, pmlp, b_fc1, nullptr, ROWS, HIDDEN, 1024, 1024, HIDDEN, HIDDEN);
    // 9) fc2 + bias + residual(x1) -> out
    sgemm_kernel<2><<<dim3(WIDTH / 128, ROWS / 128), 256>>>(
        pmlp, w_fc2, out, b_fc2, px1, ROWS, WIDTH, HIDDEN, HIDDEN, WIDTH, WIDTH);
}

// round 5
// speedup vs baseline: 1.6640x; 1.6640x over previous
#include <cuda_runtime.h>
#include <cuda_bf16.h>
#include <math.h>
#include <stdint.h>

#define WIDTH    1024
#define HEADS    16
#define HEAD_DIM 64
#define HIDDEN   4096
#define BATCH    2
#define SEQ      2048
#define ROWS     (BATCH * SEQ)   /* 4096 */
#define BH       (BATCH * HEADS) /* 32 */

// ---------------- scratch (device globals: no allocation allowed) ----------------
__device__ float g_h[ROWS * WIDTH];
__device__ float g_qkv[ROWS * 3 * WIDTH];
__device__ float g_scores[(size_t)BH * SEQ * SEQ];      // 512 MB
__device__ float g_attnout[ROWS * WIDTH];
__device__ float g_x1[ROWS * WIDTH];
__device__ float g_mlp[(size_t)ROWS * HIDDEN];

// transposed + bf16-split weights: [N][K] K-major
__device__ __nv_bfloat16 g_wqkv_h[3072 * 1024];
__device__ __nv_bfloat16 g_wqkv_l[3072 * 1024];
__device__ __nv_bfloat16 g_wproj_h[1024 * 1024];
__device__ __nv_bfloat16 g_wproj_l[1024 * 1024];
__device__ __nv_bfloat16 g_wfc1_h[4096 * 1024];
__device__ __nv_bfloat16 g_wfc1_l[4096 * 1024];
__device__ __nv_bfloat16 g_wfc2_h[1024 * 4096];
__device__ __nv_bfloat16 g_wfc2_l[1024 * 4096];

// ---------------- helpers ----------------
__device__ __forceinline__ uint32_t smem_u32(const void* p) {
    uint32_t a;
    asm("{ .reg .u64 t; cvta.to.shared.u64 t, %1; cvt.u32.u64 %0, t; }" : "=r"(a) : "l"(p));
    return a;
}

__device__ __forceinline__ void ldsm_x4(uint32_t& r0, uint32_t& r1, uint32_t& r2, uint32_t& r3, uint32_t addr) {
    asm volatile("ldmatrix.sync.aligned.m8n8.x4.shared.b16 {%0,%1,%2,%3}, [%4];"
        : "=r"(r0), "=r"(r1), "=r"(r2), "=r"(r3) : "r"(addr));
}

__device__ __forceinline__ void mma16816(float* c, const uint32_t* a, const uint32_t* b) {
    asm volatile("mma.sync.aligned.m16n8k16.row.col.f32.bf16.bf16.f32 "
        "{%0,%1,%2,%3}, {%4,%5,%6,%7}, {%8,%9}, {%0,%1,%2,%3};"
        : "+f"(c[0]), "+f"(c[1]), "+f"(c[2]), "+f"(c[3])
        : "r"(a[0]), "r"(a[1]), "r"(a[2]), "r"(a[3]), "r"(b[0]), "r"(b[1]));
}

__device__ __forceinline__ float gelu_exact(float x) {
    return 0.5f * x * (1.0f + erff(x * 0.70710678118654752440f));
}

__device__ __forceinline__ uint32_t pack_bf16_hi(float a, float b) {
    __nv_bfloat162 p;
    p.x = __float2bfloat16_rn(a);
    p.y = __float2bfloat16_rn(b);
    return *(uint32_t*)&p;
}
__device__ __forceinline__ uint32_t pack_bf16_lo(float a, float b, uint32_t hi) {
    __nv_bfloat162 h = *(__nv_bfloat162*)&hi;
    __nv_bfloat162 p;
    p.x = __float2bfloat16_rn(a - __bfloat162float(h.x));
    p.y = __float2bfloat16_rn(b - __bfloat162float(h.y));
    return *(uint32_t*)&p;
}

__device__ __forceinline__ float block_sum256(float v, volatile float* red) {
    int t = threadIdx.x;
    #pragma unroll
    for (int o = 16; o > 0; o >>= 1) v += __shfl_xor_sync(0xffffffffu, v, o);
    if ((t & 31) == 0) red[t >> 5] = v;
    __syncthreads();
    if (t < 32) {
        float r = (t < 8) ? red[t] : 0.0f;
        #pragma unroll
        for (int o = 4; o > 0; o >>= 1) r += __shfl_xor_sync(0xffffffffu, r, o);
        if (t == 0) red[0] = r;
    }
    __syncthreads();
    float r = red[0];
    __syncthreads();
    return r;
}

__device__ __forceinline__ float block_max256(float v, volatile float* red) {
    int t = threadIdx.x;
    #pragma unroll
    for (int o = 16; o > 0; o >>= 1) v = fmaxf(v, __shfl_xor_sync(0xffffffffu, v, o));
    if ((t & 31) == 0) red[t >> 5] = v;
    __syncthreads();
    if (t < 32) {
        float r = (t < 8) ? red[t] : -INFINITY;
        #pragma unroll
        for (int o = 4; o > 0; o >>= 1) r = fmaxf(r, __shfl_xor_sync(0xffffffffu, r, o));
        if (t == 0) red[0] = r;
    }
    __syncthreads();
    float r = red[0];
    __syncthreads();
    return r;
}

// ---------------- weight transpose + bf16 split: W[K][N] -> Th/Tl[N][K] ----------------
__global__ void __launch_bounds__(256) wsplit_kernel(
    const float* __restrict__ W, __nv_bfloat16* __restrict__ Th,
    __nv_bfloat16* __restrict__ Tl, int Kdim, int Ndim)
{
    __shared__ float tile[32][33];
    int bx = blockIdx.x * 32;  // N
    int by = blockIdx.y * 32;  // K
    int tx = threadIdx.x & 31;
    int ty = threadIdx.x >> 5;
    #pragma unroll
    for (int i = 0; i < 32; i += 8)
        tile[ty + i][tx] = W[(size_t)(by + ty + i) * Ndim + bx + tx];
    __syncthreads();
    #pragma unroll
    for (int i = 0; i < 32; i += 8) {
        float v = tile[tx][ty + i];
        __nv_bfloat16 h = __float2bfloat16_rn(v);
        __nv_bfloat16 l = __float2bfloat16_rn(v - __bfloat162float(h));
        size_t o = (size_t)(bx + ty + i) * Kdim + by + tx;
        Th[o] = h;
        Tl[o] = l;
    }
}

// ---------------- LayerNorm ----------------
__global__ void __launch_bounds__(256) layernorm_kernel(
    const float* __restrict__ x, const float* __restrict__ g,
    const float* __restrict__ b, float* __restrict__ out)
{
    __shared__ float red[32];
    int row = blockIdx.x;
    int t = threadIdx.x;
    const float4* xin = (const float4*)(x + (size_t)row * WIDTH);
    float4 v = xin[t];

    float s = v.x + v.y + v.z + v.w;
    float mu = block_sum256(s, red) * (1.0f / WIDTH);

    float d0 = v.x - mu, d1 = v.y - mu, d2 = v.z - mu, d3 = v.w - mu;
    float ss = d0 * d0 + d1 * d1 + d2 * d2 + d3 * d3;
    float var = block_sum256(ss, red) * (1.0f / WIDTH);
    float rstd = rsqrtf(var + 1e-5f);

    float4 gg = ((const float4*)g)[t];
    float4 bb = ((const float4*)b)[t];
    float4 o4;
    o4.x = d0 * rstd * gg.x + bb.x;
    o4.y = d1 * rstd * gg.y + bb.y;
    o4.z = d2 * rstd * gg.z + bb.z;
    o4.w = d3 * rstd * gg.w + bb.w;
    ((float4*)(out + (size_t)row * WIDTH))[t] = o4;
}

// ============ mma.sync bf16-split GEMM: C[M,N] = A[M,K](f32) @ Bt[N,K](bf16 hi/lo) =========
// 128x128 CTA tile, K-chunk 32, 8 warps (2 M x 4 N), warp tile 64x32.
// EPI: 0 none, 2 bias+res, 3 bias+GELU
#define RS 40   /* smem row stride in bf16 (80 B: conflict-free ldmatrix) */

template <int EPI>
__global__ void __launch_bounds__(256) mma_gemm_kernel(
    const float* __restrict__ A,
    const __nv_bfloat16* __restrict__ Bth, const __nv_bfloat16* __restrict__ Btl,
    float* __restrict__ C, const float* __restrict__ bias, const float* __restrict__ res,
    int M, int N, int K, int lda, int ldc)
{
    __shared__ __align__(16) __nv_bfloat16 Ash[128 * RS];
    __shared__ __align__(16) __nv_bfloat16 Asl[128 * RS];
    __shared__ __align__(16) __nv_bfloat16 Bsh[128 * RS];
    __shared__ __align__(16) __nv_bfloat16 Bsl[128 * RS];

    const int tid = threadIdx.x;
    const int wid = tid >> 5;
    const int lane = tid & 31;
    const int bm = blockIdx.y * 128;
    const int bn = blockIdx.x * 128;
    const int wm = (wid >> 2) * 64;   // warp M offset
    const int wn = (wid & 3) * 32;    // warp N offset

    const uint32_t sAh = smem_u32(Ash);
    const uint32_t sAl = smem_u32(Asl);
    const uint32_t sBh = smem_u32(Bsh);
    const uint32_t sBl = smem_u32(Bsl);

    float c[4][4][4];
    #pragma unroll
    for (int i = 0; i < 4; i++)
        #pragma unroll
        for (int j = 0; j < 4; j++)
            #pragma unroll
            for (int q = 0; q < 4; q++) c[i][j][q] = 0.0f;

    // staging maps
    const int a_f4  = tid;                 // +256*i; row = f4>>3, c4 = (f4&7)*4
    const int b_u4  = tid;                 // +256*i; row = u>>2, c8 = (u&3)*8

    float4 av[4];
    uint4 bvh[2], bvl[2];

    const int nchunks = K >> 5;

    // prefetch chunk 0
    {
        #pragma unroll
        for (int i = 0; i < 4; i++) {
            int f4 = a_f4 + 256 * i;
            int row = f4 >> 3, c4 = (f4 & 7) << 2;
            av[i] = *(const float4*)(A + (size_t)(bm + row) * lda + c4);
        }
        #pragma unroll
        for (int i = 0; i < 2; i++) {
            int u = b_u4 + 256 * i;
            int row = u >> 2, c8 = (u & 3) << 3;
            size_t off = (size_t)(bn + row) * K + c8;
            bvh[i] = *(const uint4*)(Bth + off);
            bvl[i] = *(const uint4*)(Btl + off);
        }
    }

    for (int ch = 0; ch < nchunks; ch++) {
        __syncthreads();   // previous compute done reading smem
        // ---- convert + STS ----
        #pragma unroll
        for (int i = 0; i < 4; i++) {
            int f4 = a_f4 + 256 * i;
            int row = f4 >> 3, c4 = (f4 & 7) << 2;
            float4 v = av[i];
            uint32_t h0 = pack_bf16_hi(v.x, v.y);
            uint32_t h1 = pack_bf16_hi(v.z, v.w);
            uint32_t l0 = pack_bf16_lo(v.x, v.y, h0);
            uint32_t l1 = pack_bf16_lo(v.z, v.w, h1);
            uint32_t off = (uint32_t)(row * RS + c4) * 2;
            *(uint2*)((char*)Ash + off) = make_uint2(h0, h1);
            *(uint2*)((char*)Asl + off) = make_uint2(l0, l1);
        }
        #pragma unroll
        for (int i = 0; i < 2; i++) {
            int u = b_u4 + 256 * i;
            int row = u >> 2, c8 = (u & 3) << 3;
            uint32_t off = (uint32_t)(row * RS + c8) * 2;
            *(uint4*)((char*)Bsh + off) = bvh[i];
            *(uint4*)((char*)Bsl + off) = bvl[i];
        }
        __syncthreads();

        // ---- prefetch next chunk ----
        if (ch + 1 < nchunks) {
            const int kk = (ch + 1) << 5;
            #pragma unroll
            for (int i = 0; i < 4; i++) {
                int f4 = a_f4 + 256 * i;
                int row = f4 >> 3, c4 = (f4 & 7) << 2;
                av[i] = *(const float4*)(A + (size_t)(bm + row) * lda + kk + c4);
            }
            #pragma unroll
            for (int i = 0; i < 2; i++) {
                int u = b_u4 + 256 * i;
                int row = u >> 2, c8 = (u & 3) << 3;
                size_t off = (size_t)(bn + row) * K + kk + c8;
                bvh[i] = *(const uint4*)(Bth + off);
                bvl[i] = *(const uint4*)(Btl + off);
            }
        }

        // ---- compute: 2 k16 steps ----
        #pragma unroll
        for (int ks = 0; ks < 2; ks++) {
            uint32_t ah[4][4], al[4][4], bh[4][2], bl[4][2];
            // A fragments: lanes 0-15 rows, lanes>=16 k+8
            {
                int arow = wm + (lane & 15);
                int acol = ks * 16 + ((lane >> 4) << 3);
                #pragma unroll
                for (int mt = 0; mt < 4; mt++) {
                    uint32_t off = (uint32_t)((arow + mt * 16) * RS + acol) * 2;
                    ldsm_x4(ah[mt][0], ah[mt][1], ah[mt][2], ah[mt][3], sAh + off);
                    ldsm_x4(al[mt][0], al[mt][1], al[mt][2], al[mt][3], sAl + off);
                }
            }
            // B fragments: x4 covers two n8 tiles
            {
                int brow = wn + (lane & 7) + ((lane >> 4) << 3);
                int bcol = ks * 16 + (((lane >> 3) & 1) << 3);
                #pragma unroll
                for (int p = 0; p < 2; p++) {
                    uint32_t off = (uint32_t)((brow + p * 16) * RS + bcol) * 2;
                    ldsm_x4(bh[2 * p][0], bh[2 * p][1], bh[2 * p + 1][0], bh[2 * p + 1][1], sBh + off);
                    ldsm_x4(bl[2 * p][0], bl[2 * p][1], bl[2 * p + 1][0], bl[2 * p + 1][1], sBl + off);
                }
            }
            #pragma unroll
            for (int mt = 0; mt < 4; mt++)
                #pragma unroll
                for (int nt = 0; nt < 4; nt++) {
                    mma16816(c[mt][nt], ah[mt], bh[nt]);
                    mma16816(c[mt][nt], ah[mt], bl[nt]);
                    mma16816(c[mt][nt], al[mt], bh[nt]);
                }
        }
    }

    // ---- epilogue ----
    #pragma unroll
    for (int mt = 0; mt < 4; mt++) {
        #pragma unroll
        for (int nt = 0; nt < 4; nt++) {
            int r0 = bm + wm + mt * 16 + (lane >> 2);
            int col = bn + wn + nt * 8 + (lane & 3) * 2;
            #pragma unroll
            for (int half = 0; half < 2; half++) {
                int row = r0 + half * 8;
                float v0 = c[mt][nt][half * 2 + 0];
                float v1 = c[mt][nt][half * 2 + 1];
                if (EPI >= 2) { v0 += bias[col]; v1 += bias[col + 1]; }
                if (EPI == 2) {
                    const float* rp = res + (size_t)row * ldc + col;
                    v0 += rp[0]; v1 += rp[1];
                }
                if (EPI == 3) { v0 = gelu_exact(v0); v1 = gelu_exact(v1); }
                float2 o; o.x = v0; o.y = v1;
                *(float2*)(C + (size_t)row * ldc + col) = o;
            }
        }
    }
}

// ---------------- attention scores (fp32 FFMA) ----------------
__global__ void __launch_bounds__(256) attn_scores_kernel(
    const float* __restrict__ qkv, float* __restrict__ S)
{
    __shared__ float Qs[64][68];
    __shared__ float Ks[64][68];

    const int jt = blockIdx.x;
    const int it = blockIdx.y;
    const int bh = blockIdx.z;
    const int b = bh >> 4, h = bh & 15;
    const int tid = threadIdx.x;

    const size_t qbase = (size_t)(b * SEQ + it * 64) * 3072 + h * 64;
    const size_t kbase = (size_t)(b * SEQ + jt * 64) * 3072 + 1024 + h * 64;

    #pragma unroll
    for (int q = 0; q < 4; q++) {
        int f = tid + 256 * q;
        int row = f >> 4;
        int c4 = (f & 15) << 2;
        float4 qv = *(const float4*)(qkv + qbase + (size_t)row * 3072 + c4);
        float4 kv = *(const float4*)(qkv + kbase + (size_t)row * 3072 + c4);
        Qs[c4 + 0][row] = qv.x; Qs[c4 + 1][row] = qv.y;
        Qs[c4 + 2][row] = qv.z; Qs[c4 + 3][row] = qv.w;
        Ks[c4 + 0][row] = kv.x; Ks[c4 + 1][row] = kv.y;
        Ks[c4 + 2][row] = kv.z; Ks[c4 + 3][row] = kv.w;
    }
    __syncthreads();

    const int ti = (tid >> 4) << 2;
    const int tj = (tid & 15) << 2;
    float acc[4][4] = {};
    #pragma unroll 8
    for (int d = 0; d < 64; d++) {
        float4 a = *(const float4*)&Qs[d][ti];
        float4 bb = *(const float4*)&Ks[d][tj];
        float aa[4] = {a.x, a.y, a.z, a.w};
        float bv[4] = {bb.x, bb.y, bb.z, bb.w};
        #pragma unroll
        for (int i = 0; i < 4; i++)
            #pragma unroll
            for (int j = 0; j < 4; j++) acc[i][j] = fmaf(aa[i], bv[j], acc[i][j]);
    }

    const float scale = 0.125f;
    size_t base = (size_t)bh * SEQ * SEQ;
    #pragma unroll
    for (int i = 0; i < 4; i++) {
        size_t roff = base + (size_t)(it * 64 + ti + i) * SEQ + jt * 64 + tj;
        float4 o;
        o.x = acc[i][0] * scale; o.y = acc[i][1] * scale;
        o.z = acc[i][2] * scale; o.w = acc[i][3] * scale;
        *(float4*)(S + roff) = o;
    }
}

// ---------------- softmax ----------------
__global__ void __launch_bounds__(256) softmax_kernel(float* __restrict__ S)
{
    __shared__ float red[32];
    size_t row = (size_t)blockIdx.y * SEQ + blockIdx.x;
    float* p = S + row * SEQ;
    int t = threadIdx.x;

    float4 a = ((const float4*)p)[t];
    float4 b = ((const float4*)p)[t + 256];
    float m = fmaxf(fmaxf(fmaxf(a.x, a.y), fmaxf(a.z, a.w)),
                    fmaxf(fmaxf(b.x, b.y), fmaxf(b.z, b.w)));
    m = block_max256(m, red);

    a.x = expf(a.x - m); a.y = expf(a.y - m); a.z = expf(a.z - m); a.w = expf(a.w - m);
    b.x = expf(b.x - m); b.y = expf(b.y - m); b.z = expf(b.z - m); b.w = expf(b.w - m);
    float s = a.x + a.y + a.z + a.w + b.x + b.y + b.z + b.w;
    s = block_sum256(s, red);
    float inv = 1.0f / s;

    a.x *= inv; a.y *= inv; a.z *= inv; a.w *= inv;
    b.x *= inv; b.y *= inv; b.z *= inv; b.w *= inv;
    ((float4*)p)[t] = a;
    ((float4*)p)[t + 256] = b;
}

// ---------------- PV (fp32 FFMA) ----------------
__global__ void __launch_bounds__(256) attn_pv_kernel(
    const float* __restrict__ S, const float* __restrict__ qkv, float* __restrict__ out)
{
    __shared__ float As[8][128];
    __shared__ float Bs[8][64];

    const int bh = blockIdx.y;
    const int b = bh >> 4, h = bh & 15;
    const float* A = S + (size_t)bh * SEQ * SEQ;
    const float* V = qkv + (size_t)b * SEQ * 3072 + 2048 + h * 64;
    float* C = out + (size_t)b * SEQ * WIDTH + h * 64;

    const int bm = blockIdx.x * 128;
    const int tid = threadIdx.x;
    const int tr = (tid >> 3) << 2;
    const int tc = (tid & 7) << 3;

    float acc[4][8];
    #pragma unroll
    for (int i = 0; i < 4; i++)
        #pragma unroll
        for (int j = 0; j < 8; j++) acc[i][j] = 0.0f;

    const int a_row = tid >> 1;
    const int a_k   = (tid & 1) << 2;
    const int b_k   = tid >> 4;
    const int b_col = (tid & 15) << 2;

    const float* Aptr = A + (size_t)(bm + a_row) * SEQ + a_k;
    const float* Bptr = V + (size_t)b_k * 3072 + b_col;

    for (int kk = 0; kk < SEQ; kk += 8) {
        float4 av = *(const float4*)Aptr;
        float4 bv = make_float4(0.f, 0.f, 0.f, 0.f);
        if (tid < 128) bv = *(const float4*)Bptr;
        __syncthreads();
        As[a_k + 0][a_row] = av.x;
        As[a_k + 1][a_row] = av.y;
        As[a_k + 2][a_row] = av.z;
        As[a_k + 3][a_row] = av.w;
        if (tid < 128) *(float4*)&Bs[b_k][b_col] = bv;
        __syncthreads();
        #pragma unroll
        for (int k = 0; k < 8; k++) {
            float4 a0 = *(const float4*)&As[k][tr];
            float4 b0 = *(const float4*)&Bs[k][tc];
            float4 b1 = *(const float4*)&Bs[k][tc + 4];
            float aa[4] = {a0.x, a0.y, a0.z, a0.w};
            float bb[8] = {b0.x, b0.y, b0.z, b0.w, b1.x, b1.y, b1.z, b1.w};
            #pragma unroll
            for (int i = 0; i < 4; i++)
                #pragma unroll
                for (int j = 0; j < 8; j++) acc[i][j] = fmaf(aa[i], bb[j], acc[i][j]);
        }
        Aptr += 8;
        Bptr += (size_t)8 * 3072;
    }

    #pragma unroll
    for (int i = 0; i < 4; i++) {
        #pragma unroll
        for (int j = 0; j < 8; j += 4) {
            float4 o;
            o.x = acc[i][j + 0]; o.y = acc[i][j + 1];
            o.z = acc[i][j + 2]; o.w = acc[i][j + 3];
            *(float4*)(C + (size_t)(bm + tr + i) * WIDTH + tc + j) = o;
        }
    }
}

// ---------------- launch ----------------
extern "C" void kernel_launch(void* const* d_in, const int* in_sizes, int n_in,
                              void* d_out, int out_size)
{
    const float* x      = (const float*)d_in[0];
    const float* ln1_g  = (const float*)d_in[1];
    const float* ln1_b  = (const float*)d_in[2];
    const float* w_qkv  = (const float*)d_in[3];
    const float* w_proj = (const float*)d_in[4];
    const float* b_proj = (const float*)d_in[5];
    const float* ln2_g  = (const float*)d_in[6];
    const float* ln2_b  = (const float*)d_in[7];
    const float* w_fc1  = (const float*)d_in[8];
    const float* b_fc1  = (const float*)d_in[9];
    const float* w_fc2  = (const float*)d_in[10];
    const float* b_fc2  = (const float*)d_in[11];
    float* out = (float*)d_out;

    float *ph, *pqkv, *pscore, *pattn, *px1, *pmlp;
    cudaGetSymbolAddress((void**)&ph,     g_h);
    cudaGetSymbolAddress((void**)&pqkv,   g_qkv);
    cudaGetSymbolAddress((void**)&pscore, g_scores);
    cudaGetSymbolAddress((void**)&pattn,  g_attnout);
    cudaGetSymbolAddress((void**)&px1,    g_x1);
    cudaGetSymbolAddress((void**)&pmlp,   g_mlp);

    __nv_bfloat16 *qkv_h, *qkv_l, *proj_h, *proj_l, *fc1_h, *fc1_l, *fc2_h, *fc2_l;
    cudaGetSymbolAddress((void**)&qkv_h,  g_wqkv_h);
    cudaGetSymbolAddress((void**)&qkv_l,  g_wqkv_l);
    cudaGetSymbolAddress((void**)&proj_h, g_wproj_h);
    cudaGetSymbolAddress((void**)&proj_l, g_wproj_l);
    cudaGetSymbolAddress((void**)&fc1_h,  g_wfc1_h);
    cudaGetSymbolAddress((void**)&fc1_l,  g_wfc1_l);
    cudaGetSymbolAddress((void**)&fc2_h,  g_wfc2_h);
    cudaGetSymbolAddress((void**)&fc2_l,  g_wfc2_l);

    // 0) weight transpose + split
    wsplit_kernel<<<dim3(3072 / 32, 1024 / 32), 256>>>(w_qkv,  qkv_h,  qkv_l,  1024, 3072);
    wsplit_kernel<<<dim3(1024 / 32, 1024 / 32), 256>>>(w_proj, proj_h, proj_l, 1024, 1024);
    wsplit_kernel<<<dim3(4096 / 32, 1024 / 32), 256>>>(w_fc1,  fc1_h,  fc1_l,  1024, 4096);
    wsplit_kernel<<<dim3(1024 / 32, 4096 / 32), 256>>>(w_fc2,  fc2_h,  fc2_l,  4096, 1024);

    // 1) LN1
    layernorm_kernel<<<ROWS, 256>>>(x, ln1_g, ln1_b, ph);
    // 2) QKV GEMM (mma.sync bf16 split)
    mma_gemm_kernel<0><<<dim3(3072 / 128, ROWS / 128), 256>>>(
        ph, qkv_h, qkv_l, pqkv, nullptr, nullptr, ROWS, 3072, 1024, 1024, 3072);
    // 3) scores
    attn_scores_kernel<<<dim3(SEQ / 64, SEQ / 64, BH), 256>>>(pqkv, pscore);
    // 4) softmax
    softmax_kernel<<<dim3(SEQ, BH), 256>>>(pscore);
    // 5) PV
    attn_pv_kernel<<<dim3(SEQ / 128, BH), 256>>>(pscore, pqkv, pattn);
    // 6) proj + bias + residual(x)
    mma_gemm_kernel<2><<<dim3(WIDTH / 128, ROWS / 128), 256>>>(
        pattn, proj_h, proj_l, px1, b_proj, x, ROWS, WIDTH, 1024, 1024, WIDTH);
    // 7) LN2
    layernorm_kernel<<<ROWS, 256>>>(px1, ln2_g, ln2_b, ph);
    // 8) fc1 + bias + GELU
    mma_gemm_kernel<3><<<dim3(HIDDEN / 128, ROWS / 128), 256>>>(
        ph, fc1_h, fc1_l, pmlp, b_fc1, nullptr, ROWS, HIDDEN, 1024, 1024, HIDDEN);
    // 9) fc2 + bias + residual(x1) -> out
    mma_gemm_kernel<2><<<dim3(WIDTH / 128, ROWS / 128), 256>>>(
        pmlp, fc2_h, fc2_l, out, b_fc2, px1, ROWS, WIDTH, 4096, 4096, WIDTH);
}

// round 6
// speedup vs baseline: 2.8466x; 1.7107x over previous
#include <cuda_runtime.h>
#include <cuda_bf16.h>
#include <math.h>
#include <stdint.h>

#define WIDTH    1024
#define HEADS    16
#define HEAD_DIM 64
#define HIDDEN   4096
#define BATCH    2
#define SEQ      2048
#define ROWS     (BATCH * SEQ)   /* 4096 */
#define BH       (BATCH * HEADS) /* 32 */

// ---------------- scratch ----------------
__device__ float g_h[ROWS * WIDTH];
__device__ float g_qkv[ROWS * 3 * WIDTH];
__device__ float g_attnout[ROWS * WIDTH];
__device__ float g_x1[ROWS * WIDTH];
__device__ float g_mlp[(size_t)ROWS * HIDDEN];

__device__ __nv_bfloat16 g_wqkv_h[3072 * 1024];
__device__ __nv_bfloat16 g_wqkv_l[3072 * 1024];
__device__ __nv_bfloat16 g_wproj_h[1024 * 1024];
__device__ __nv_bfloat16 g_wproj_l[1024 * 1024];
__device__ __nv_bfloat16 g_wfc1_h[4096 * 1024];
__device__ __nv_bfloat16 g_wfc1_l[4096 * 1024];
__device__ __nv_bfloat16 g_wfc2_h[1024 * 4096];
__device__ __nv_bfloat16 g_wfc2_l[1024 * 4096];

// ---------------- helpers ----------------
__device__ __forceinline__ uint32_t smem_u32(const void* p) {
    uint32_t a;
    asm("{ .reg .u64 t; cvta.to.shared.u64 t, %1; cvt.u32.u64 %0, t; }" : "=r"(a) : "l"(p));
    return a;
}

__device__ __forceinline__ void ldsm_x4(uint32_t& r0, uint32_t& r1, uint32_t& r2, uint32_t& r3, uint32_t addr) {
    asm volatile("ldmatrix.sync.aligned.m8n8.x4.shared.b16 {%0,%1,%2,%3}, [%4];"
        : "=r"(r0), "=r"(r1), "=r"(r2), "=r"(r3) : "r"(addr));
}

__device__ __forceinline__ void mma16816(float* c, const uint32_t* a, const uint32_t* b) {
    asm volatile("mma.sync.aligned.m16n8k16.row.col.f32.bf16.bf16.f32 "
        "{%0,%1,%2,%3}, {%4,%5,%6,%7}, {%8,%9}, {%0,%1,%2,%3};"
        : "+f"(c[0]), "+f"(c[1]), "+f"(c[2]), "+f"(c[3])
        : "r"(a[0]), "r"(a[1]), "r"(a[2]), "r"(a[3]), "r"(b[0]), "r"(b[1]));
}

__device__ __forceinline__ float gelu_exact(float x) {
    return 0.5f * x * (1.0f + erff(x * 0.70710678118654752440f));
}

__device__ __forceinline__ uint32_t pack_bf16_hi(float a, float b) {
    __nv_bfloat162 p;
    p.x = __float2bfloat16_rn(a);
    p.y = __float2bfloat16_rn(b);
    return *(uint32_t*)&p;
}
__device__ __forceinline__ uint32_t pack_bf16_lo(float a, float b, uint32_t hi) {
    __nv_bfloat162 h = *(__nv_bfloat162*)&hi;
    __nv_bfloat162 p;
    p.x = __float2bfloat16_rn(a - __bfloat162float(h.x));
    p.y = __float2bfloat16_rn(b - __bfloat162float(h.y));
    return *(uint32_t*)&p;
}

__device__ __forceinline__ float block_sum256(float v, volatile float* red) {
    int t = threadIdx.x;
    #pragma unroll
    for (int o = 16; o > 0; o >>= 1) v += __shfl_xor_sync(0xffffffffu, v, o);
    if ((t & 31) == 0) red[t >> 5] = v;
    __syncthreads();
    if (t < 32) {
        float r = (t < 8) ? red[t] : 0.0f;
        #pragma unroll
        for (int o = 4; o > 0; o >>= 1) r += __shfl_xor_sync(0xffffffffu, r, o);
        if (t == 0) red[0] = r;
    }
    __syncthreads();
    float r = red[0];
    __syncthreads();
    return r;
}

// ---------------- weight transpose + bf16 split ----------------
__global__ void __launch_bounds__(256) wsplit_kernel(
    const float* __restrict__ W, __nv_bfloat16* __restrict__ Th,
    __nv_bfloat16* __restrict__ Tl, int Kdim, int Ndim)
{
    __shared__ float tile[32][33];
    int bx = blockIdx.x * 32;
    int by = blockIdx.y * 32;
    int tx = threadIdx.x & 31;
    int ty = threadIdx.x >> 5;
    #pragma unroll
    for (int i = 0; i < 32; i += 8)
        tile[ty + i][tx] = W[(size_t)(by + ty + i) * Ndim + bx + tx];
    __syncthreads();
    #pragma unroll
    for (int i = 0; i < 32; i += 8) {
        float v = tile[tx][ty + i];
        __nv_bfloat16 h = __float2bfloat16_rn(v);
        __nv_bfloat16 l = __float2bfloat16_rn(v - __bfloat162float(h));
        size_t o = (size_t)(bx + ty + i) * Kdim + by + tx;
        Th[o] = h;
        Tl[o] = l;
    }
}

// ---------------- LayerNorm ----------------
__global__ void __launch_bounds__(256) layernorm_kernel(
    const float* __restrict__ x, const float* __restrict__ g,
    const float* __restrict__ b, float* __restrict__ out)
{
    __shared__ float red[32];
    int row = blockIdx.x;
    int t = threadIdx.x;
    const float4* xin = (const float4*)(x + (size_t)row * WIDTH);
    float4 v = xin[t];

    float s = v.x + v.y + v.z + v.w;
    float mu = block_sum256(s, red) * (1.0f / WIDTH);

    float d0 = v.x - mu, d1 = v.y - mu, d2 = v.z - mu, d3 = v.w - mu;
    float ss = d0 * d0 + d1 * d1 + d2 * d2 + d3 * d3;
    float var = block_sum256(ss, red) * (1.0f / WIDTH);
    float rstd = rsqrtf(var + 1e-5f);

    float4 gg = ((const float4*)g)[t];
    float4 bb = ((const float4*)b)[t];
    float4 o4;
    o4.x = d0 * rstd * gg.x + bb.x;
    o4.y = d1 * rstd * gg.y + bb.y;
    o4.z = d2 * rstd * gg.z + bb.z;
    o4.w = d3 * rstd * gg.w + bb.w;
    ((float4*)(out + (size_t)row * WIDTH))[t] = o4;
}

// ============ mma.sync bf16-split dense GEMM (unchanged from R5) ============
#define RS 40

template <int EPI>
__global__ void __launch_bounds__(256) mma_gemm_kernel(
    const float* __restrict__ A,
    const __nv_bfloat16* __restrict__ Bth, const __nv_bfloat16* __restrict__ Btl,
    float* __restrict__ C, const float* __restrict__ bias, const float* __restrict__ res,
    int M, int N, int K, int lda, int ldc)
{
    __shared__ __align__(16) __nv_bfloat16 Ash[128 * RS];
    __shared__ __align__(16) __nv_bfloat16 Asl[128 * RS];
    __shared__ __align__(16) __nv_bfloat16 Bsh[128 * RS];
    __shared__ __align__(16) __nv_bfloat16 Bsl[128 * RS];

    const int tid = threadIdx.x;
    const int wid = tid >> 5;
    const int lane = tid & 31;
    const int bm = blockIdx.y * 128;
    const int bn = blockIdx.x * 128;
    const int wm = (wid >> 2) * 64;
    const int wn = (wid & 3) * 32;

    const uint32_t sAh = smem_u32(Ash);
    const uint32_t sAl = smem_u32(Asl);
    const uint32_t sBh = smem_u32(Bsh);
    const uint32_t sBl = smem_u32(Bsl);

    float c[4][4][4];
    #pragma unroll
    for (int i = 0; i < 4; i++)
        #pragma unroll
        for (int j = 0; j < 4; j++)
            #pragma unroll
            for (int q = 0; q < 4; q++) c[i][j][q] = 0.0f;

    const int a_f4 = tid;
    const int b_u4 = tid;

    float4 av[4];
    uint4 bvh[2], bvl[2];

    const int nchunks = K >> 5;

    {
        #pragma unroll
        for (int i = 0; i < 4; i++) {
            int f4 = a_f4 + 256 * i;
            int row = f4 >> 3, c4 = (f4 & 7) << 2;
            av[i] = *(const float4*)(A + (size_t)(bm + row) * lda + c4);
        }
        #pragma unroll
        for (int i = 0; i < 2; i++) {
            int u = b_u4 + 256 * i;
            int row = u >> 2, c8 = (u & 3) << 3;
            size_t off = (size_t)(bn + row) * K + c8;
            bvh[i] = *(const uint4*)(Bth + off);
            bvl[i] = *(const uint4*)(Btl + off);
        }
    }

    for (int ch = 0; ch < nchunks; ch++) {
        __syncthreads();
        #pragma unroll
        for (int i = 0; i < 4; i++) {
            int f4 = a_f4 + 256 * i;
            int row = f4 >> 3, c4 = (f4 & 7) << 2;
            float4 v = av[i];
            uint32_t h0 = pack_bf16_hi(v.x, v.y);
            uint32_t h1 = pack_bf16_hi(v.z, v.w);
            uint32_t l0 = pack_bf16_lo(v.x, v.y, h0);
            uint32_t l1 = pack_bf16_lo(v.z, v.w, h1);
            uint32_t off = (uint32_t)(row * RS + c4) * 2;
            *(uint2*)((char*)Ash + off) = make_uint2(h0, h1);
            *(uint2*)((char*)Asl + off) = make_uint2(l0, l1);
        }
        #pragma unroll
        for (int i = 0; i < 2; i++) {
            int u = b_u4 + 256 * i;
            int row = u >> 2, c8 = (u & 3) << 3;
            uint32_t off = (uint32_t)(row * RS + c8) * 2;
            *(uint4*)((char*)Bsh + off) = bvh[i];
            *(uint4*)((char*)Bsl + off) = bvl[i];
        }
        __syncthreads();

        if (ch + 1 < nchunks) {
            const int kk = (ch + 1) << 5;
            #pragma unroll
            for (int i = 0; i < 4; i++) {
                int f4 = a_f4 + 256 * i;
                int row = f4 >> 3, c4 = (f4 & 7) << 2;
                av[i] = *(const float4*)(A + (size_t)(bm + row) * lda + kk + c4);
            }
            #pragma unroll
            for (int i = 0; i < 2; i++) {
                int u = b_u4 + 256 * i;
                int row = u >> 2, c8 = (u & 3) << 3;
                size_t off = (size_t)(bn + row) * K + kk + c8;
                bvh[i] = *(const uint4*)(Bth + off);
                bvl[i] = *(const uint4*)(Btl + off);
            }
        }

        #pragma unroll
        for (int ks = 0; ks < 2; ks++) {
            uint32_t ah[4][4], al[4][4], bh[4][2], bl[4][2];
            {
                int arow = wm + (lane & 15);
                int acol = ks * 16 + ((lane >> 4) << 3);
                #pragma unroll
                for (int mt = 0; mt < 4; mt++) {
                    uint32_t off = (uint32_t)((arow + mt * 16) * RS + acol) * 2;
                    ldsm_x4(ah[mt][0], ah[mt][1], ah[mt][2], ah[mt][3], sAh + off);
                    ldsm_x4(al[mt][0], al[mt][1], al[mt][2], al[mt][3], sAl + off);
                }
            }
            {
                int brow = wn + (lane & 7) + ((lane >> 4) << 3);
                int bcol = ks * 16 + (((lane >> 3) & 1) << 3);
                #pragma unroll
                for (int p = 0; p < 2; p++) {
                    uint32_t off = (uint32_t)((brow + p * 16) * RS + bcol) * 2;
                    ldsm_x4(bh[2 * p][0], bh[2 * p][1], bh[2 * p + 1][0], bh[2 * p + 1][1], sBh + off);
                    ldsm_x4(bl[2 * p][0], bl[2 * p][1], bl[2 * p + 1][0], bl[2 * p + 1][1], sBl + off);
                }
            }
            #pragma unroll
            for (int mt = 0; mt < 4; mt++)
                #pragma unroll
                for (int nt = 0; nt < 4; nt++) {
                    mma16816(c[mt][nt], ah[mt], bh[nt]);
                    mma16816(c[mt][nt], ah[mt], bl[nt]);
                    mma16816(c[mt][nt], al[mt], bh[nt]);
                }
        }
    }

    #pragma unroll
    for (int mt = 0; mt < 4; mt++) {
        #pragma unroll
        for (int nt = 0; nt < 4; nt++) {
            int r0 = bm + wm + mt * 16 + (lane >> 2);
            int col = bn + wn + nt * 8 + (lane & 3) * 2;
            #pragma unroll
            for (int half = 0; half < 2; half++) {
                int row = r0 + half * 8;
                float v0 = c[mt][nt][half * 2 + 0];
                float v1 = c[mt][nt][half * 2 + 1];
                if (EPI >= 2) { v0 += bias[col]; v1 += bias[col + 1]; }
                if (EPI == 2) {
                    const float* rp = res + (size_t)row * ldc + col;
                    v0 += rp[0]; v1 += rp[1];
                }
                if (EPI == 3) { v0 = gelu_exact(v0); v1 = gelu_exact(v1); }
                float2 o; o.x = v0; o.y = v1;
                *(float2*)(C + (size_t)row * ldc + col) = o;
            }
        }
    }
}

// ============ fused flash attention (mma.sync bf16-split, online softmax) ============
// grid (16 qtiles, 32 bh); 8 warps; warp w owns Q rows [w*16, w*16+16), full 128-key S extent.
// smem: Qh/Ql, Kh/Kl: 128x72 bf16; Vt h/l: 64x136 bf16 (transposed).
#define FQ_RS 72
#define FV_RS 136
#define S_QH  0
#define S_QL  18432
#define S_KH  36864
#define S_KL  55296
#define S_VH  73728
#define S_VL  91136
#define FLASH_SMEM 108544

__global__ void __launch_bounds__(256, 1) flash_attn_kernel(
    const float* __restrict__ qkv, float* __restrict__ out)
{
    extern __shared__ char fsm[];
    const int tid = threadIdx.x;
    const int wid = tid >> 5;
    const int lane = tid & 31;
    const int qt = blockIdx.x;
    const int bh = blockIdx.y;
    const int b = bh >> 4, h = bh & 15;

    const uint32_t sb = smem_u32(fsm);
    const uint32_t sQH = sb + S_QH, sQL = sb + S_QL;
    const uint32_t sKH = sb + S_KH, sKL = sb + S_KL;
    const uint32_t sVH = sb + S_VH, sVL = sb + S_VL;

    // ---- load Q tile (128x64 f32), split to bf16 hi/lo ----
    {
        const float* Qg = qkv + (size_t)(b * SEQ + qt * 128) * 3072 + h * 64;
        #pragma unroll
        for (int i = 0; i < 8; i++) {
            int idx = tid + 256 * i;
            int row = idx >> 4, c4 = (idx & 15) << 2;
            float4 v = *(const float4*)(Qg + (size_t)row * 3072 + c4);
            uint32_t h0 = pack_bf16_hi(v.x, v.y);
            uint32_t h1 = pack_bf16_hi(v.z, v.w);
            uint32_t l0 = pack_bf16_lo(v.x, v.y, h0);
            uint32_t l1 = pack_bf16_lo(v.z, v.w, h1);
            uint32_t off = (uint32_t)(row * FQ_RS + c4) * 2;
            *(uint2*)(fsm + S_QH + off) = make_uint2(h0, h1);
            *(uint2*)(fsm + S_QL + off) = make_uint2(l0, l1);
        }
    }
    __syncthreads();

    // ---- Q fragments (persist across KV loop) ----
    uint32_t qh[4][4], ql[4][4];
    {
        int arow = wid * 16 + (lane & 15);
        #pragma unroll
        for (int ks = 0; ks < 4; ks++) {
            int acol = ks * 16 + ((lane >> 4) << 3);
            uint32_t off = (uint32_t)(arow * FQ_RS + acol) * 2;
            ldsm_x4(qh[ks][0], qh[ks][1], qh[ks][2], qh[ks][3], sQH + off);
            ldsm_x4(ql[ks][0], ql[ks][1], ql[ks][2], ql[ks][3], sQL + off);
        }
    }

    float m0 = -1e30f, m1 = -1e30f, l0s = 0.0f, l1s = 0.0f;
    float o[8][4];
    #pragma unroll
    for (int i = 0; i < 8; i++)
        #pragma unroll
        for (int j = 0; j < 4; j++) o[i][j] = 0.0f;

    const float* Kg = qkv + (size_t)b * SEQ * 3072 + 1024 + h * 64;
    const float* Vg = qkv + (size_t)b * SEQ * 3072 + 2048 + h * 64;

    for (int kt = 0; kt < 16; kt++) {
        // ---- stage K/V tile loads in registers ----
        float4 kv4[8], vv4[8];
        #pragma unroll
        for (int i = 0; i < 8; i++) {
            int idx = tid + 256 * i;
            int key = idx >> 4, c4 = (idx & 15) << 2;
            size_t go = (size_t)(kt * 128 + key) * 3072 + c4;
            kv4[i] = *(const float4*)(Kg + go);
            vv4[i] = *(const float4*)(Vg + go);
        }
        __syncthreads();   // previous iteration's fragment reads done
        #pragma unroll
        for (int i = 0; i < 8; i++) {
            int idx = tid + 256 * i;
            int key = idx >> 4, c4 = (idx & 15) << 2;
            {
                float4 v = kv4[i];
                uint32_t h0 = pack_bf16_hi(v.x, v.y);
                uint32_t h1 = pack_bf16_hi(v.z, v.w);
                uint32_t l0 = pack_bf16_lo(v.x, v.y, h0);
                uint32_t l1 = pack_bf16_lo(v.z, v.w, h1);
                uint32_t off = (uint32_t)(key * FQ_RS + c4) * 2;
                *(uint2*)(fsm + S_KH + off) = make_uint2(h0, h1);
                *(uint2*)(fsm + S_KL + off) = make_uint2(l0, l1);
            }
            {
                float4 v = vv4[i];
                float vals[4] = {v.x, v.y, v.z, v.w};
                #pragma unroll
                for (int j = 0; j < 4; j++) {
                    __nv_bfloat16 hh = __float2bfloat16_rn(vals[j]);
                    __nv_bfloat16 ll = __float2bfloat16_rn(vals[j] - __bfloat162float(hh));
                    uint32_t off = (uint32_t)((c4 + j) * FV_RS + key) * 2;
                    *(__nv_bfloat16*)(fsm + S_VH + off) = hh;
                    *(__nv_bfloat16*)(fsm + S_VL + off) = ll;
                }
            }
        }
        __syncthreads();

        // ---- S = Q @ K^T (16 n-tiles x 4 k-steps x 3 products) ----
        float s[16][4];
        #pragma unroll
        for (int nt = 0; nt < 16; nt++)
            #pragma unroll
            for (int j = 0; j < 4; j++) s[nt][j] = 0.0f;

        #pragma unroll
        for (int ks = 0; ks < 4; ks++) {
            int bcol = ks * 16 + (((lane >> 3) & 1) << 3);
            #pragma unroll
            for (int p = 0; p < 8; p++) {
                int brow = p * 16 + (lane & 7) + ((lane >> 4) << 3);
                uint32_t off = (uint32_t)(brow * FQ_RS + bcol) * 2;
                uint32_t bhr[2][2], blr[2][2];
                ldsm_x4(bhr[0][0], bhr[0][1], bhr[1][0], bhr[1][1], sKH + off);
                ldsm_x4(blr[0][0], blr[0][1], blr[1][0], blr[1][1], sKL + off);
                #pragma unroll
                for (int q = 0; q < 2; q++) {
                    mma16816(s[2 * p + q], qh[ks], bhr[q]);
                    mma16816(s[2 * p + q], qh[ks], blr[q]);
                    mma16816(s[2 * p + q], ql[ks], bhr[q]);
                }
            }
        }

        // ---- online softmax (warp-local; rows r=lane>>2 and r+8) ----
        #pragma unroll
        for (int nt = 0; nt < 16; nt++) {
            s[nt][0] *= 0.125f; s[nt][1] *= 0.125f;
            s[nt][2] *= 0.125f; s[nt][3] *= 0.125f;
        }
        float mt0 = -1e30f, mt1 = -1e30f;
        #pragma unroll
        for (int nt = 0; nt < 16; nt++) {
            mt0 = fmaxf(mt0, fmaxf(s[nt][0], s[nt][1]));
            mt1 = fmaxf(mt1, fmaxf(s[nt][2], s[nt][3]));
        }
        mt0 = fmaxf(mt0, __shfl_xor_sync(0xffffffffu, mt0, 1));
        mt0 = fmaxf(mt0, __shfl_xor_sync(0xffffffffu, mt0, 2));
        mt1 = fmaxf(mt1, __shfl_xor_sync(0xffffffffu, mt1, 1));
        mt1 = fmaxf(mt1, __shfl_xor_sync(0xffffffffu, mt1, 2));

        float mn0 = fmaxf(m0, mt0), mn1 = fmaxf(m1, mt1);
        float corr0 = __expf(m0 - mn0), corr1 = __expf(m1 - mn1);
        float rs0 = 0.0f, rs1 = 0.0f;
        #pragma unroll
        for (int nt = 0; nt < 16; nt++) {
            s[nt][0] = __expf(s[nt][0] - mn0);
            s[nt][1] = __expf(s[nt][1] - mn0);
            s[nt][2] = __expf(s[nt][2] - mn1);
            s[nt][3] = __expf(s[nt][3] - mn1);
            rs0 += s[nt][0] + s[nt][1];
            rs1 += s[nt][2] + s[nt][3];
        }
        rs0 += __shfl_xor_sync(0xffffffffu, rs0, 1);
        rs0 += __shfl_xor_sync(0xffffffffu, rs0, 2);
        rs1 += __shfl_xor_sync(0xffffffffu, rs1, 1);
        rs1 += __shfl_xor_sync(0xffffffffu, rs1, 2);
        l0s = l0s * corr0 + rs0;
        l1s = l1s * corr1 + rs1;
        m0 = mn0; m1 = mn1;
        #pragma unroll
        for (int nt = 0; nt < 8; nt++) {
            o[nt][0] *= corr0; o[nt][1] *= corr0;
            o[nt][2] *= corr1; o[nt][3] *= corr1;
        }

        // ---- pack P hi/lo as A fragments (C-frag layout == A-frag layout) ----
        uint32_t ph[8][4], pl[8][4];
        #pragma unroll
        for (int k2 = 0; k2 < 8; k2++) {
            int t0 = 2 * k2, t1 = t0 + 1;
            ph[k2][0] = pack_bf16_hi(s[t0][0], s[t0][1]);
            ph[k2][1] = pack_bf16_hi(s[t0][2], s[t0][3]);
            ph[k2][2] = pack_bf16_hi(s[t1][0], s[t1][1]);
            ph[k2][3] = pack_bf16_hi(s[t1][2], s[t1][3]);
            pl[k2][0] = pack_bf16_lo(s[t0][0], s[t0][1], ph[k2][0]);
            pl[k2][1] = pack_bf16_lo(s[t0][2], s[t0][3], ph[k2][1]);
            pl[k2][2] = pack_bf16_lo(s[t1][0], s[t1][1], ph[k2][2]);
            pl[k2][3] = pack_bf16_lo(s[t1][2], s[t1][3], ph[k2][3]);
        }

        // ---- O += P @ V  (8 d-tiles x 8 k-steps x 3 products) ----
        #pragma unroll
        for (int k2 = 0; k2 < 8; k2++) {
            int bcol = k2 * 16 + (((lane >> 3) & 1) << 3);
            #pragma unroll
            for (int p = 0; p < 4; p++) {
                int brow = p * 16 + (lane & 7) + ((lane >> 4) << 3);
                uint32_t off = (uint32_t)(brow * FV_RS + bcol) * 2;
                uint32_t vhr[2][2], vlr[2][2];
                ldsm_x4(vhr[0][0], vhr[0][1], vhr[1][0], vhr[1][1], sVH + off);
                ldsm_x4(vlr[0][0], vlr[0][1], vlr[1][0], vlr[1][1], sVL + off);
                #pragma unroll
                for (int q = 0; q < 2; q++) {
                    mma16816(o[2 * p + q], ph[k2], vhr[q]);
                    mma16816(o[2 * p + q], ph[k2], vlr[q]);
                    mma16816(o[2 * p + q], pl[k2], vhr[q]);
                }
            }
        }
    }

    // ---- finalize: O /= l, write out ----
    float inv0 = 1.0f / l0s, inv1 = 1.0f / l1s;
    int row0 = qt * 128 + wid * 16 + (lane >> 2);
    #pragma unroll
    for (int nt = 0; nt < 8; nt++) {
        int col = h * 64 + nt * 8 + (lane & 3) * 2;
        float2 v0; v0.x = o[nt][0] * inv0; v0.y = o[nt][1] * inv0;
        float2 v1; v1.x = o[nt][2] * inv1; v1.y = o[nt][3] * inv1;
        *(float2*)(out + (size_t)(b * SEQ + row0) * WIDTH + col) = v0;
        *(float2*)(out + (size_t)(b * SEQ + row0 + 8) * WIDTH + col) = v1;
    }
}

// ---------------- launch ----------------
extern "C" void kernel_launch(void* const* d_in, const int* in_sizes, int n_in,
                              void* d_out, int out_size)
{
    const float* x      = (const float*)d_in[0];
    const float* ln1_g  = (const float*)d_in[1];
    const float* ln1_b  = (const float*)d_in[2];
    const float* w_qkv  = (const float*)d_in[3];
    const float* w_proj = (const float*)d_in[4];
    const float* b_proj = (const float*)d_in[5];
    const float* ln2_g  = (const float*)d_in[6];
    const float* ln2_b  = (const float*)d_in[7];
    const float* w_fc1  = (const float*)d_in[8];
    const float* b_fc1  = (const float*)d_in[9];
    const float* w_fc2  = (const float*)d_in[10];
    const float* b_fc2  = (const float*)d_in[11];
    float* out = (float*)d_out;

    float *ph, *pqkv, *pattn, *px1, *pmlp;
    cudaGetSymbolAddress((void**)&ph,    g_h);
    cudaGetSymbolAddress((void**)&pqkv,  g_qkv);
    cudaGetSymbolAddress((void**)&pattn, g_attnout);
    cudaGetSymbolAddress((void**)&px1,   g_x1);
    cudaGetSymbolAddress((void**)&pmlp,  g_mlp);

    __nv_bfloat16 *qkv_h, *qkv_l, *proj_h, *proj_l, *fc1_h, *fc1_l, *fc2_h, *fc2_l;
    cudaGetSymbolAddress((void**)&qkv_h,  g_wqkv_h);
    cudaGetSymbolAddress((void**)&qkv_l,  g_wqkv_l);
    cudaGetSymbolAddress((void**)&proj_h, g_wproj_h);
    cudaGetSymbolAddress((void**)&proj_l, g_wproj_l);
    cudaGetSymbolAddress((void**)&fc1_h,  g_wfc1_h);
    cudaGetSymbolAddress((void**)&fc1_l,  g_wfc1_l);
    cudaGetSymbolAddress((void**)&fc2_h,  g_wfc2_h);
    cudaGetSymbolAddress((void**)&fc2_l,  g_wfc2_l);

    static bool attr_done = false;
    if (!attr_done) {
        cudaFuncSetAttribute(flash_attn_kernel, cudaFuncAttributeMaxDynamicSharedMemorySize, FLASH_SMEM);
        attr_done = true;
    }

    // 0) weight transpose + split
    wsplit_kernel<<<dim3(3072 / 32, 1024 / 32), 256>>>(w_qkv,  qkv_h,  qkv_l,  1024, 3072);
    wsplit_kernel<<<dim3(1024 / 32, 1024 / 32), 256>>>(w_proj, proj_h, proj_l, 1024, 1024);
    wsplit_kernel<<<dim3(4096 / 32, 1024 / 32), 256>>>(w_fc1,  fc1_h,  fc1_l,  1024, 4096);
    wsplit_kernel<<<dim3(1024 / 32, 4096 / 32), 256>>>(w_fc2,  fc2_h,  fc2_l,  4096, 1024);

    // 1) LN1
    layernorm_kernel<<<ROWS, 256>>>(x, ln1_g, ln1_b, ph);
    // 2) QKV GEMM
    mma_gemm_kernel<0><<<dim3(3072 / 128, ROWS / 128), 256>>>(
        ph, qkv_h, qkv_l, pqkv, nullptr, nullptr, ROWS, 3072, 1024, 1024, 3072);
    // 3) fused flash attention
    flash_attn_kernel<<<dim3(16, BH), 256, FLASH_SMEM>>>(pqkv, pattn);
    // 4) proj + bias + residual(x)
    mma_gemm_kernel<2><<<dim3(WIDTH / 128, ROWS / 128), 256>>>(
        pattn, proj_h, proj_l, px1, b_proj, x, ROWS, WIDTH, 1024, 1024, WIDTH);
    // 5) LN2
    layernorm_kernel<<<ROWS, 256>>>(px1, ln2_g, ln2_b, ph);
    // 6) fc1 + bias + GELU
    mma_gemm_kernel<3><<<dim3(HIDDEN / 128, ROWS / 128), 256>>>(
        ph, fc1_h, fc1_l, pmlp, b_fc1, nullptr, ROWS, HIDDEN, 1024, 1024, HIDDEN);
    // 7) fc2 + bias + residual(x1) -> out
    mma_gemm_kernel<2><<<dim3(WIDTH / 128, ROWS / 128), 256>>>(
        pmlp, fc2_h, fc2_l, out, b_fc2, px1, ROWS, WIDTH, 4096, 4096, WIDTH);
}